// round 13
// baseline (speedup 1.0000x reference)
#include <cuda_runtime.h>
#include <cuda_bf16.h>
#include <cstdint>

#define G  32
#define NV 64
#define H  256
#define M_ROWS (G * NV)
#define GRID 512

// Scratch (allocation-free rule: __device__ globals)
__device__ float g_C[M_ROWS * H];
__device__ float g_Y[M_ROWS * H];
__device__ unsigned long long g_bar;   // epoch barrier counter (monotonic)

#define KC   32
#define LDK  36
#define NCH  (H / KC)   // 8 chunks

__device__ __forceinline__ void cpa16(uint32_t dst, const float* src) {
    asm volatile("cp.async.cg.shared.global [%0], [%1], 16;" :: "r"(dst), "l"(src));
}

__device__ __forceinline__ void mma_tf32(float c[4], const uint32_t a[4], const uint32_t b[2]) {
    asm volatile(
        "mma.sync.aligned.m16n8k8.row.col.f32.tf32.tf32.f32 "
        "{%0,%1,%2,%3}, {%4,%5,%6,%7}, {%8,%9}, {%0,%1,%2,%3};"
        : "+f"(c[0]), "+f"(c[1]), "+f"(c[2]), "+f"(c[3])
        : "r"(a[0]), "r"(a[1]), "r"(a[2]), "r"(a[3]), "r"(b[0]), "r"(b[1]));
}

__device__ __forceinline__ float tanhx(float x) {
    float th;
    asm("tanh.approx.f32 %0, %1;" : "=f"(th) : "f"(x));
    return th;
}

// Shared memory union: GEMM staging vs attn Y-slab (max 36864 B, static)
union SmemU {
    struct { float As[2][64 * LDK]; float Bs[2][64 * LDK]; } g;
    struct { float ysh[64 * 128]; } a;
};

// ---------------------------------------------------------------------------
// Fused kernel: [compaction] -> [GEMM tile if b<256] -> global barrier ->
// [attn unit b].
// GEMM: TF32 HMMA (raw fp32 bits as tf32), 64x64 tile, KC=32 double-buffered.
// attn: unit = (rchunk 0..7, graph 0..31, h-half 0..1). 8 warps x 8 rows,
//       lane owns a float4 of the 128-float half-row. One compacted cp.async
//       fill, one barrier, linear LDS.128 -> FFMA(imm) -> MUFU.TANH -> FADD.
// sigmoid(x)=0.5*tanh(0.5*x)+0.5 folded into FFMA/epilogue.
// ---------------------------------------------------------------------------
__global__ void __launch_bounds__(256, 4) fused_kernel(
    const float* __restrict__ z,
    const float* __restrict__ Wc, const float* __restrict__ bc,
    const float* __restrict__ Wy, const float* __restrict__ by,
    const float* __restrict__ mask, float* __restrict__ out)
{
    __shared__ SmemU su;
    __shared__ int acts[NV];
    __shared__ int s_cnt[2];
    __shared__ int s_nact;

    const int t = threadIdx.x;
    const int b = blockIdx.x;

    // ---- compaction for this block's graph (overlaps the GEMM phase) ----
    const int gg = (b >> 3) & 31;
    {
        bool act = false;
        unsigned bal = 0;
        if (t < NV) {
            act = (mask[gg * NV + t] > 0.5f);
            bal = __ballot_sync(0xffffffffu, act);
            if ((t & 31) == 0) s_cnt[t >> 5] = __popc(bal);
        }
        __syncthreads();
        if (t < NV) {
            const int warp = t >> 5, lane = t & 31;
            const int a0 = s_cnt[0], a1 = s_cnt[1];
            const int nact = a0 + a1;
            const int pre  = __popc(bal & ((1u << lane) - 1u));
            const int preI = lane - pre;
            const int pos = act ? ((warp ? a0 : 0) + pre)
                                : (nact + (warp ? (32 - a0) : 0) + preI);
            acts[pos] = t;
            if (t == 0) s_nact = nact;
        }
        __syncthreads();
    }

    // ---- Phase A: GEMM tile (blocks 0..255) ----
    if (b < 256) {
        const int  which = b >> 7;                 // 0: C, 1: Y
        const float* __restrict__ W    = which ? Wy : Wc;
        const float* __restrict__ bias = which ? by : bc;
        float* __restrict__ outp       = which ? g_Y : g_C;
        const int n0 = (b & 3) * 64;
        const int m0 = ((b >> 2) & 31) * 64;

        const int warp = t >> 5;
        const int lane = t & 31;
        const int gq   = lane >> 2;
        const int tg   = lane & 3;
        const int wm   = warp & 3;
        const int wn   = warp >> 2;

        const int r0s = t >> 3,         kg0 = t & 7;
        const int r1s = (t + 256) >> 3, kg1 = (t + 256) & 7;

        float acc[4][4];
#pragma unroll
        for (int nt = 0; nt < 4; nt++)
#pragma unroll
            for (int i = 0; i < 4; i++) acc[nt][i] = 0.0f;

        auto issue = [&](int c) {
            const int buf = c & 1;
            const int kc0 = c * KC;
            uint32_t asb = (uint32_t)__cvta_generic_to_shared(&su.g.As[buf][0]);
            uint32_t bsb = (uint32_t)__cvta_generic_to_shared(&su.g.Bs[buf][0]);
            cpa16(asb + (uint32_t)(r0s * LDK + kg0 * 4) * 4, z + (size_t)(m0 + r0s) * H + kc0 + kg0 * 4);
            cpa16(asb + (uint32_t)(r1s * LDK + kg1 * 4) * 4, z + (size_t)(m0 + r1s) * H + kc0 + kg1 * 4);
            cpa16(bsb + (uint32_t)(r0s * LDK + kg0 * 4) * 4, W + (size_t)(n0 + r0s) * H + kc0 + kg0 * 4);
            cpa16(bsb + (uint32_t)(r1s * LDK + kg1 * 4) * 4, W + (size_t)(n0 + r1s) * H + kc0 + kg1 * 4);
            asm volatile("cp.async.commit_group;");
        };

        issue(0);

        for (int c = 0; c < NCH; c++) {
            if (c + 1 < NCH) {
                issue(c + 1);
                asm volatile("cp.async.wait_group 1;");
            } else {
                asm volatile("cp.async.wait_group 0;");
            }
            __syncthreads();

            const uint32_t* as = reinterpret_cast<const uint32_t*>(&su.g.As[c & 1][0]);
            const uint32_t* bs = reinterpret_cast<const uint32_t*>(&su.g.Bs[c & 1][0]);

#pragma unroll
            for (int ks = 0; ks < KC / 8; ks++) {
                const int kk = ks * 8;
                uint32_t afr[4];
                {
                    const uint32_t* ap = as + (wm * 16 + gq) * LDK + kk + tg;
                    afr[0] = ap[0];
                    afr[1] = ap[8 * LDK];
                    afr[2] = ap[4];
                    afr[3] = ap[8 * LDK + 4];
                }
                uint32_t bfr[4][2];
#pragma unroll
                for (int nt = 0; nt < 4; nt++) {
                    const uint32_t* bp = bs + (wn * 32 + nt * 8 + gq) * LDK + kk + tg;
                    bfr[nt][0] = bp[0];
                    bfr[nt][1] = bp[4];
                }
#pragma unroll
                for (int nt = 0; nt < 4; nt++)
                    mma_tf32(acc[nt], afr, bfr[nt]);
            }
            __syncthreads();
        }

#pragma unroll
        for (int nt = 0; nt < 4; nt++) {
            const int col = n0 + wn * 32 + nt * 8 + 2 * tg;
            const float b0 = __ldg(&bias[col]);
            const float b1 = __ldg(&bias[col + 1]);
            const int row = m0 + wm * 16 + gq;
            float2 o0 = {acc[nt][0] + b0, acc[nt][1] + b1};
            float2 o1 = {acc[nt][2] + b0, acc[nt][3] + b1};
            *reinterpret_cast<float2*>(&outp[(size_t)row * H + col])       = o0;
            *reinterpret_cast<float2*>(&outp[(size_t)(row + 8) * H + col]) = o1;
        }
    }

    // ---- global barrier (epoch-based; replay-safe; all 512 resident) ----
    __syncthreads();
    if (t == 0) {
        __threadfence();
        unsigned long long ticket = atomicAdd(&g_bar, 1ULL);
        unsigned long long target = (ticket / GRID + 1ULL) * (unsigned long long)GRID;
        unsigned long long v;
        for (;;) {
            asm volatile("ld.global.acquire.gpu.u64 %0, [%1];" : "=l"(v) : "l"(&g_bar));
            if (v >= target) break;
            asm volatile("nanosleep.u32 128;");
        }
    }
    __syncthreads();

    // ---- Phase B: attention unit b = (rchunk, gg, half) ----
    const int rchunk = b & 7;
    const int half   = b >> 8;
    const int nact   = s_nact;
    const int lane   = t & 31;
    const int w      = t >> 5;
    const int rr     = rchunk * 8 + w;
    const int row_i  = acts[rr];

    float4* __restrict__ outp4 = reinterpret_cast<float4*>(
        out + (size_t)gg * NV * H + (size_t)row_i * H + half * 128) + lane;

    if (rchunk * 8 >= nact) {            // fully inactive unit
        outp4[0] = make_float4(0.0f, 0.0f, 0.0f, 0.0f);
        return;
    }

    // compacted fill: smem row k = Y[acts[k]][half*128 .. +128)
    {
        const float* __restrict__ ygb = g_Y + (size_t)gg * NV * H + half * 128;
        const uint32_t sb = (uint32_t)__cvta_generic_to_shared(&su.a.ysh[0]);
        const int nch = nact * 32;               // 16B chunks (32 per row)
        for (int s = t; s < nch; s += 256) {
            const int rw = s >> 5;
            const int q  = s & 31;
            cpa16(sb + (uint32_t)(rw * 128 + q * 4) * 4,
                  ygb + (size_t)acts[rw] * H + q * 4);
        }
        asm volatile("cp.async.commit_group;");
    }

    float4 a2, acc;
    {
        const float4 c = __ldg(reinterpret_cast<const float4*>(
            g_C + (size_t)gg * NV * H + (size_t)row_i * H + half * 128) + lane);
        a2.x = 0.5f * c.x; a2.y = 0.5f * c.y;
        a2.z = 0.5f * c.z; a2.w = 0.5f * c.w;
        acc.x = acc.y = acc.z = acc.w = 0.0f;
    }

    asm volatile("cp.async.wait_group 0;");
    __syncthreads();

    const float4* __restrict__ ys4 = reinterpret_cast<const float4*>(su.a.ysh);

    int jj = 0;
    for (; jj + 4 <= nact; jj += 4) {
        float4 yv[4];
#pragma unroll
        for (int u = 0; u < 4; u++) yv[u] = ys4[(jj + u) * 32 + lane];
#pragma unroll
        for (int u = 0; u < 4; u++) {
            acc.x += tanhx(fmaf(0.5f, yv[u].x, a2.x));
            acc.y += tanhx(fmaf(0.5f, yv[u].y, a2.y));
            acc.z += tanhx(fmaf(0.5f, yv[u].z, a2.z));
            acc.w += tanhx(fmaf(0.5f, yv[u].w, a2.w));
        }
    }
    for (; jj < nact; jj++) {
        const float4 y = ys4[jj * 32 + lane];
        acc.x += tanhx(fmaf(0.5f, y.x, a2.x));
        acc.y += tanhx(fmaf(0.5f, y.y, a2.y));
        acc.z += tanhx(fmaf(0.5f, y.z, a2.z));
        acc.w += tanhx(fmaf(0.5f, y.w, a2.w));
    }

    const float inv    = 1.0f / (float)nact;
    const float half_n = 0.5f * (float)nact;
    float4 v;
    if (rr < nact) {                     // straddling unit's tail rows -> 0
        v.x = (0.5f * acc.x + half_n) * inv;
        v.y = (0.5f * acc.y + half_n) * inv;
        v.z = (0.5f * acc.z + half_n) * inv;
        v.w = (0.5f * acc.w + half_n) * inv;
    } else {
        v.x = v.y = v.z = v.w = 0.0f;
    }
    outp4[0] = v;
}

// ---------------------------------------------------------------------------
// kernel_launch
// ---------------------------------------------------------------------------
extern "C" void kernel_launch(void* const* d_in, const int* in_sizes, int n_in,
                              void* d_out, int out_size)
{
    const float *z = nullptr, *mask = nullptr;
    const float *Wc = nullptr, *bc = nullptr, *Wy = nullptr, *by = nullptr;

    for (int i = 0; i < n_in; i++) {
        int s = in_sizes[i];
        const float* p = (const float*)d_in[i];
        if (s == M_ROWS * H)       z = p;
        else if (s == M_ROWS)      mask = p;
        else if (s == H * H)       { if (!Wc) Wc = p; else Wy = p; }
        else if (s == H)           { if (!bc) bc = p; else by = p; }
    }

    float* out = (float*)d_out;

    fused_kernel<<<GRID, 256>>>(z, Wc, bc, Wy, by, mask, out);
}

// round 14
// speedup vs baseline: 1.1098x; 1.1098x over previous
#include <cuda_runtime.h>
#include <cuda_bf16.h>
#include <cstdint>

#define G  32
#define NV 64
#define H  256
#define M_ROWS (G * NV)
#define GRID 512

// Scratch (allocation-free rule: __device__ globals)
__device__ float g_C[M_ROWS * H];
__device__ float g_Y[M_ROWS * H];
__device__ unsigned long long g_bar;   // epoch barrier counter (monotonic)

#define KC   32
#define LDK  36
#define NCH  (H / KC)   // 8 chunks

__device__ __forceinline__ void cpa16(uint32_t dst, const float* src) {
    asm volatile("cp.async.cg.shared.global [%0], [%1], 16;" :: "r"(dst), "l"(src));
}

__device__ __forceinline__ void mma_tf32(float c[4], const uint32_t a[4], const uint32_t b[2]) {
    asm volatile(
        "mma.sync.aligned.m16n8k8.row.col.f32.tf32.tf32.f32 "
        "{%0,%1,%2,%3}, {%4,%5,%6,%7}, {%8,%9}, {%0,%1,%2,%3};"
        : "+f"(c[0]), "+f"(c[1]), "+f"(c[2]), "+f"(c[3])
        : "r"(a[0]), "r"(a[1]), "r"(a[2]), "r"(a[3]), "r"(b[0]), "r"(b[1]));
}

__device__ __forceinline__ float tanhx(float x) {
    float th;
    asm("tanh.approx.f32 %0, %1;" : "=f"(th) : "f"(x));
    return th;
}

// Shared memory union: GEMM staging (27648 B) vs attn double-buffer (16384 B)
union SmemU {
    struct { float As[2][32 * LDK]; float Bs[2][64 * LDK]; } g;
    struct { float ysh[2][16 * 128]; } a;
};

// ---------------------------------------------------------------------------
// Fused kernel, 512 blocks (all resident; 4/SM guaranteed):
//   [compaction (overlaps phase A)] -> [GEMM tile b: 32x64, ALL blocks] ->
//   global epoch barrier -> [attn unit b = (rchunk, graph, half)].
// GEMM: TF32 HMMA (raw fp32 bits as tf32), KC=32 double-buffered cp.async,
//       8 warps, warp tile 16x16.
// attn: 8 warps x 8 rows, lane owns float4 of the 128-float half-row.
//       16-row chunked, double-buffered compacted fill overlapped with the
//       LDS.128 -> FFMA(imm 0.5) -> MUFU.TANH -> FADD loop.
// sigmoid(x)=0.5*tanh(0.5*x)+0.5 folded into FFMA/epilogue.
// ---------------------------------------------------------------------------
__global__ void __launch_bounds__(256, 4) fused_kernel(
    const float* __restrict__ z,
    const float* __restrict__ Wc, const float* __restrict__ bc,
    const float* __restrict__ Wy, const float* __restrict__ by,
    const float* __restrict__ mask, float* __restrict__ out)
{
    __shared__ SmemU su;
    __shared__ int acts[NV];
    __shared__ int s_cnt[2];
    __shared__ int s_nact;

    const int t = threadIdx.x;
    const int b = blockIdx.x;

    // ---- compaction for this block's attn graph (overlaps phase A) ----
    const int gg = (b >> 3) & 31;
    {
        bool act = false;
        unsigned bal = 0;
        if (t < NV) {
            act = (mask[gg * NV + t] > 0.5f);
            bal = __ballot_sync(0xffffffffu, act);
            if ((t & 31) == 0) s_cnt[t >> 5] = __popc(bal);
        }
        __syncthreads();
        if (t < NV) {
            const int warp = t >> 5, lane = t & 31;
            const int a0 = s_cnt[0], a1 = s_cnt[1];
            const int nact = a0 + a1;
            const int pre  = __popc(bal & ((1u << lane) - 1u));
            const int preI = lane - pre;
            const int pos = act ? ((warp ? a0 : 0) + pre)
                                : (nact + (warp ? (32 - a0) : 0) + preI);
            acts[pos] = t;
            if (t == 0) s_nact = nact;
        }
        __syncthreads();
    }

    // ---- Phase A: GEMM tile (ALL 512 blocks; 32x64 tile each) ----
    {
        const int which = b >> 8;                  // 0: C, 1: Y
        const int idx   = b & 255;
        const float* __restrict__ W    = which ? Wy : Wc;
        const float* __restrict__ bias = which ? by : bc;
        float* __restrict__ outp       = which ? g_Y : g_C;
        const int m0 = (idx >> 2) * 32;            // 64 m-tiles
        const int n0 = (idx & 3) * 64;             // 4 n-tiles

        const int warp = t >> 5;
        const int lane = t & 31;
        const int gq   = lane >> 2;
        const int tg   = lane & 3;
        const int wm   = warp & 1;                 // 2 warps along M (16 each)
        const int wn   = warp >> 1;                // 4 warps along N (16 each)

        // staging: A 256 slots (1/thread), B 512 slots (2/thread)
        const int ar = t >> 3,          akg = t & 7;
        const int br0 = t >> 3,         bk0 = t & 7;
        const int br1 = (t + 256) >> 3, bk1 = (t + 256) & 7;

        float acc[2][4];
#pragma unroll
        for (int nt = 0; nt < 2; nt++)
#pragma unroll
            for (int i = 0; i < 4; i++) acc[nt][i] = 0.0f;

        auto issue = [&](int c) {
            const int buf = c & 1;
            const int kc0 = c * KC;
            uint32_t asb = (uint32_t)__cvta_generic_to_shared(&su.g.As[buf][0]);
            uint32_t bsb = (uint32_t)__cvta_generic_to_shared(&su.g.Bs[buf][0]);
            cpa16(asb + (uint32_t)(ar  * LDK + akg * 4) * 4, z + (size_t)(m0 + ar ) * H + kc0 + akg * 4);
            cpa16(bsb + (uint32_t)(br0 * LDK + bk0 * 4) * 4, W + (size_t)(n0 + br0) * H + kc0 + bk0 * 4);
            cpa16(bsb + (uint32_t)(br1 * LDK + bk1 * 4) * 4, W + (size_t)(n0 + br1) * H + kc0 + bk1 * 4);
            asm volatile("cp.async.commit_group;");
        };

        issue(0);

        for (int c = 0; c < NCH; c++) {
            if (c + 1 < NCH) {
                issue(c + 1);
                asm volatile("cp.async.wait_group 1;");
            } else {
                asm volatile("cp.async.wait_group 0;");
            }
            __syncthreads();

            const uint32_t* as = reinterpret_cast<const uint32_t*>(&su.g.As[c & 1][0]);
            const uint32_t* bs = reinterpret_cast<const uint32_t*>(&su.g.Bs[c & 1][0]);

#pragma unroll
            for (int ks = 0; ks < KC / 8; ks++) {
                const int kk = ks * 8;
                uint32_t afr[4];
                {
                    const uint32_t* ap = as + (wm * 16 + gq) * LDK + kk + tg;
                    afr[0] = ap[0];
                    afr[1] = ap[8 * LDK];
                    afr[2] = ap[4];
                    afr[3] = ap[8 * LDK + 4];
                }
                uint32_t bfr[2][2];
#pragma unroll
                for (int nt = 0; nt < 2; nt++) {
                    const uint32_t* bp = bs + (wn * 16 + nt * 8 + gq) * LDK + kk + tg;
                    bfr[nt][0] = bp[0];
                    bfr[nt][1] = bp[4];
                }
#pragma unroll
                for (int nt = 0; nt < 2; nt++)
                    mma_tf32(acc[nt], afr, bfr[nt]);
            }
            __syncthreads();
        }

#pragma unroll
        for (int nt = 0; nt < 2; nt++) {
            const int col = n0 + wn * 16 + nt * 8 + 2 * tg;
            const float b0 = __ldg(&bias[col]);
            const float b1 = __ldg(&bias[col + 1]);
            const int row = m0 + wm * 16 + gq;
            float2 o0 = {acc[nt][0] + b0, acc[nt][1] + b1};
            float2 o1 = {acc[nt][2] + b0, acc[nt][3] + b1};
            *reinterpret_cast<float2*>(&outp[(size_t)row * H + col])       = o0;
            *reinterpret_cast<float2*>(&outp[(size_t)(row + 8) * H + col]) = o1;
        }
    }

    // ---- global barrier (epoch-based; replay-safe; all 512 resident) ----
    __syncthreads();
    if (t == 0) {
        __threadfence();
        unsigned long long ticket = atomicAdd(&g_bar, 1ULL);
        unsigned long long target = (ticket / GRID + 1ULL) * (unsigned long long)GRID;
        unsigned long long v;
        for (;;) {
            asm volatile("ld.global.acquire.gpu.u64 %0, [%1];" : "=l"(v) : "l"(&g_bar));
            if (v >= target) break;
            asm volatile("nanosleep.u32 128;");
        }
    }
    __syncthreads();

    // ---- Phase B: attention unit b = (rchunk, gg, half) ----
    const int rchunk = b & 7;
    const int half   = b >> 8;
    const int nact   = s_nact;
    const int lane   = t & 31;
    const int w      = t >> 5;
    const int rr     = rchunk * 8 + w;
    const int row_i  = acts[rr];

    float4* __restrict__ outp4 = reinterpret_cast<float4*>(
        out + (size_t)gg * NV * H + (size_t)row_i * H + half * 128) + lane;

    if (rchunk * 8 >= nact) {            // fully inactive unit
        outp4[0] = make_float4(0.0f, 0.0f, 0.0f, 0.0f);
        return;
    }

    const float* __restrict__ ygb = g_Y + (size_t)gg * NV * H + half * 128;
    const int nch = (nact + 15) >> 4;    // 16-row chunks

    auto fillc = [&](int c) {
        const int jb = c * 16;
        const int jn = min(16, nact - jb);
        const uint32_t sb = (uint32_t)__cvta_generic_to_shared(&su.a.ysh[c & 1][0]);
        const int nsl = jn * 32;                  // 16B chunks (32 per row)
        for (int s = t; s < nsl; s += 256) {
            const int rw = s >> 5;
            const int q  = s & 31;
            cpa16(sb + (uint32_t)(rw * 128 + q * 4) * 4,
                  ygb + (size_t)acts[jb + rw] * H + q * 4);
        }
        asm volatile("cp.async.commit_group;");
    };

    fillc(0);

    float4 a2, acc;
    {
        const float4 c = __ldg(reinterpret_cast<const float4*>(
            g_C + (size_t)gg * NV * H + (size_t)row_i * H + half * 128) + lane);
        a2.x = 0.5f * c.x; a2.y = 0.5f * c.y;
        a2.z = 0.5f * c.z; a2.w = 0.5f * c.w;
        acc.x = acc.y = acc.z = acc.w = 0.0f;
    }

    for (int c = 0; c < nch; c++) {
        if (c + 1 < nch) {
            fillc(c + 1);
            asm volatile("cp.async.wait_group 1;");
        } else {
            asm volatile("cp.async.wait_group 0;");
        }
        __syncthreads();

        const int jn = min(16, nact - c * 16);
        const float4* __restrict__ ys4 =
            reinterpret_cast<const float4*>(&su.a.ysh[c & 1][0]);

        int jj = 0;
        for (; jj + 4 <= jn; jj += 4) {
            float4 yv[4];
#pragma unroll
            for (int u = 0; u < 4; u++) yv[u] = ys4[(jj + u) * 32 + lane];
#pragma unroll
            for (int u = 0; u < 4; u++) {
                acc.x += tanhx(fmaf(0.5f, yv[u].x, a2.x));
                acc.y += tanhx(fmaf(0.5f, yv[u].y, a2.y));
                acc.z += tanhx(fmaf(0.5f, yv[u].z, a2.z));
                acc.w += tanhx(fmaf(0.5f, yv[u].w, a2.w));
            }
        }
        for (; jj < jn; jj++) {
            const float4 y = ys4[jj * 32 + lane];
            acc.x += tanhx(fmaf(0.5f, y.x, a2.x));
            acc.y += tanhx(fmaf(0.5f, y.y, a2.y));
            acc.z += tanhx(fmaf(0.5f, y.z, a2.z));
            acc.w += tanhx(fmaf(0.5f, y.w, a2.w));
        }
        __syncthreads();                 // buf reused by fill(c+2)
    }

    const float inv    = 1.0f / (float)nact;
    const float half_n = 0.5f * (float)nact;
    float4 v;
    if (rr < nact) {                     // straddling unit's tail rows -> 0
        v.x = (0.5f * acc.x + half_n) * inv;
        v.y = (0.5f * acc.y + half_n) * inv;
        v.z = (0.5f * acc.z + half_n) * inv;
        v.w = (0.5f * acc.w + half_n) * inv;
    } else {
        v.x = v.y = v.z = v.w = 0.0f;
    }
    outp4[0] = v;
}

// ---------------------------------------------------------------------------
// kernel_launch
// ---------------------------------------------------------------------------
extern "C" void kernel_launch(void* const* d_in, const int* in_sizes, int n_in,
                              void* d_out, int out_size)
{
    const float *z = nullptr, *mask = nullptr;
    const float *Wc = nullptr, *bc = nullptr, *Wy = nullptr, *by = nullptr;

    for (int i = 0; i < n_in; i++) {
        int s = in_sizes[i];
        const float* p = (const float*)d_in[i];
        if (s == M_ROWS * H)       z = p;
        else if (s == M_ROWS)      mask = p;
        else if (s == H * H)       { if (!Wc) Wc = p; else Wy = p; }
        else if (s == H)           { if (!bc) bc = p; else by = p; }
    }

    float* out = (float*)d_out;

    fused_kernel<<<GRID, 256>>>(z, Wc, bc, Wy, by, mask, out);
}